// round 7
// baseline (speedup 1.0000x reference)
#include <cuda_runtime.h>
#include <cuda_bf16.h>
#include <cstdint>

#define NROWS 8192
#define DDIM  1024
#define KCLS  80
#define C81   81
#define MSEL  2048
#define TOPK  100
#define NFLAT (NROWS*KCLS)
#define SCORE_T 0.05f
#define SCALE_CLAMP 4.135166556742356f
#define IMG_W 1216.0f
#define IMG_H 800.0f
#define MAX_COORD 1217.0f
#define EQ_CAP 4096
#define B_LO 15692          // bits(0.05f)>>16
#define B_N  565            // buckets up to bits(1.0f)>>16 inclusive
#define GEMM_BLOCKS 128
#define TRANS_BLOCKS 80

// ---------------- scratch (static __device__: zero-init, no allocations) ----------------
__device__ float              g_probs[NFLAT];
__device__ unsigned long long g_cand[NFLAT];
__device__ int                g_hist1[B_N];
__device__ unsigned long long g_sel[MSEL];
__device__ float4             g_bwT[KCLS*DDIM];       // [cls][k] -> 4 deltas
__device__ float              g_boxes[MSEL*4];
__device__ float              g_obox[MSEL*4];
__device__ float              g_score[MSEL];
__device__ int                g_cls[MSEL];
__device__ unsigned char      g_sup[MSEL];
__device__ unsigned char      g_valid[MSEL];
__device__ int d_nCand;
__device__ int d_done;

// ---------------- helpers ----------------
__device__ __forceinline__ float wmaxf(float v){
    #pragma unroll
    for (int o=16;o;o>>=1) v = fmaxf(v, __shfl_xor_sync(0xffffffffu, v, o));
    return v;
}
__device__ __forceinline__ float wsumf(float v){
    #pragma unroll
    for (int o=16;o;o>>=1) v += __shfl_xor_sync(0xffffffffu, v, o);
    return v;
}
__device__ __forceinline__ float lo32(unsigned long long v){ return __uint_as_float((unsigned)v); }
__device__ __forceinline__ float hi32(unsigned long long v){ return __uint_as_float((unsigned)(v>>32)); }

__device__ __forceinline__ void append_cand(bool pred, float p, int idx){
    unsigned bal = __ballot_sync(0xffffffffu, pred);
    if (!bal) return;
    int lane = threadIdx.x & 31;
    int leader = __ffs(bal) - 1;
    int base = 0;
    if (lane == leader) base = atomicAdd(&d_nCand, __popc(bal));
    base = __shfl_sync(0xffffffffu, base, leader);
    if (pred){
        unsigned u = __float_as_uint(p);
        atomicAdd(&g_hist1[(int)(u>>16) - B_LO], 1);
        int pos = base + __popc(bal & ((1u<<lane)-1u));
        g_cand[pos] = ((unsigned long long)u << 32) | (unsigned)idx;
    }
}

// ---------------- K1: cls GEMM + softmax + append; extra blocks transpose bbox_w ----------------
__global__ __launch_bounds__(256) void k_gemm_softmax(
    const float* __restrict__ x, const float* __restrict__ w, const float* __restrict__ b,
    const float* __restrict__ bw)
{
    const int tid = threadIdx.x;

    // ---- transpose blocks: bw float4 [k*80+cls] -> g_bwT[cls*1024+k] ----
    if (blockIdx.x >= GEMM_BLOCKS){
        const float4* bw4 = (const float4*)bw;
        int i0 = (blockIdx.x - GEMM_BLOCKS)*256 + tid;
        const int nT = TRANS_BLOCKS*256;
        for (int m = i0; m < KCLS*DDIM; m += nT){
            int cls = m >> 10;
            int k   = m & 1023;
            g_bwT[m] = bw4[k*KCLS + cls];
        }
        return;
    }

    __shared__ __align__(16) float xsT[32][66];
    __shared__ float ws[32][81];
    const int ty = tid >> 5, tx = tid & 31;
    const int row0 = blockIdx.x * 64;
    const bool has2 = (tx < 17);

    unsigned long long acc[4][3] = {};
    float rx[8]; float rw[11];
    {
        const float* xp = x + (size_t)row0 * DDIM;
        #pragma unroll
        for (int i=0;i<8;i++){ int e=tid+i*256; int r=e>>5, k=e&31; rx[i]=xp[(size_t)r*DDIM+k]; }
        #pragma unroll
        for (int i=0;i<11;i++){ int e=tid+i*256; if (e<32*81){ int k=e/81, c=e-k*81; rw[i]=w[(size_t)k*C81+c]; } }
    }

    for (int kc=0; kc<DDIM; kc+=32){
        #pragma unroll
        for (int i=0;i<8;i++){ int e=tid+i*256; int r=e>>5, k=e&31; xsT[k][r]=rx[i]; }
        #pragma unroll
        for (int i=0;i<11;i++){ int e=tid+i*256; if (e<32*81){ int k=e/81, c=e-k*81; ws[k][c]=rw[i]; } }
        __syncthreads();
        if (kc + 32 < DDIM){
            const float* xp = x + (size_t)row0*DDIM + kc + 32;
            const float* wp = w + (size_t)(kc+32)*C81;
            #pragma unroll
            for (int i=0;i<8;i++){ int e=tid+i*256; int r=e>>5, k=e&31; rx[i]=xp[(size_t)r*DDIM+k]; }
            #pragma unroll
            for (int i=0;i<11;i++){ int e=tid+i*256; if (e<32*81){ int k=e/81, c=e-k*81; rw[i]=wp[(size_t)k*C81+c]; } }
        }
        #pragma unroll
        for (int k=0;k<32;k++){
            float b0 = ws[k][tx];
            float b1 = ws[k][tx+32];
            float b2 = has2 ? ws[k][tx+64] : 0.f;
            unsigned long long b0d, b1d, b2d;
            asm("mov.b64 %0,{%1,%1};" : "=l"(b0d) : "f"(b0));
            asm("mov.b64 %0,{%1,%1};" : "=l"(b1d) : "f"(b1));
            asm("mov.b64 %0,{%1,%1};" : "=l"(b2d) : "f"(b2));
            #pragma unroll
            for (int p=0;p<4;p++){
                unsigned long long a = *(const unsigned long long*)&xsT[k][ty*8 + 2*p];
                asm("fma.rn.f32x2 %0,%1,%2,%0;" : "+l"(acc[p][0]) : "l"(a), "l"(b0d));
                asm("fma.rn.f32x2 %0,%1,%2,%0;" : "+l"(acc[p][1]) : "l"(a), "l"(b1d));
                asm("fma.rn.f32x2 %0,%1,%2,%0;" : "+l"(acc[p][2]) : "l"(a), "l"(b2d));
            }
        }
        __syncthreads();
    }

    const float bb0 = b[tx], bb1 = b[tx+32];
    const float bb2 = has2 ? b[tx+64] : 0.f;

    #pragma unroll
    for (int p=0;p<4;p++){
        #pragma unroll
        for (int h=0;h<2;h++){
            float l0 = (h ? hi32(acc[p][0]) : lo32(acc[p][0])) + bb0;
            float l1 = (h ? hi32(acc[p][1]) : lo32(acc[p][1])) + bb1;
            float l2 = has2 ? ((h ? hi32(acc[p][2]) : lo32(acc[p][2])) + bb2) : -3.4e38f;
            float m  = wmaxf(fmaxf(l0, fmaxf(l1, l2)));
            float e0 = expf(l0 - m), e1 = expf(l1 - m);
            float e2 = has2 ? expf(l2 - m) : 0.f;
            float s  = wsumf(e0 + e1 + e2);
            int row  = row0 + ty*8 + 2*p + h;
            float p0 = e0 / s, p1 = e1 / s;
            {
                int idx = row*KCLS + tx;
                g_probs[idx] = p0;
                append_cand(p0 > SCORE_T, p0, idx);
            }
            {
                int idx = row*KCLS + tx + 32;
                g_probs[idx] = p1;
                append_cand(p1 > SCORE_T, p1, idx);
            }
            {
                float p2 = (tx < 16) ? (e2 / s) : 0.f;
                int idx = row*KCLS + tx + 64;
                if (tx < 16) g_probs[idx] = p2;
                append_cand((tx < 16) && (p2 > SCORE_T), p2, idx);
            }
        }
    }
}

// ---------------- K2: fused selection; resets hist/d_nCand for next replay ----------------
__global__ __launch_bounds__(1024) void k_select(){
    __shared__ unsigned long long sel[MSEL];
    __shared__ unsigned se[EQ_CAP];
    __shared__ int hist[256];
    __shared__ int hA[B_N];
    __shared__ int s_nSel, s_nEq;
    __shared__ unsigned s_cut;
    __shared__ int s_r, s_B, s_nab, s_sub;
    const int t = threadIdx.x;
    const int n = d_nCand;

    for (int i=t; i<B_N; i+=1024) hA[i] = g_hist1[i];
    if (t==0){ s_nSel=0; s_nEq=0; }
    __syncthreads();
    if (t==0){
        int cum=0, B=-1, nab=0;
        for (int bi=B_N-1; bi>=0; bi--){
            int c = hA[bi];
            if (cum + c >= MSEL){ B = bi; nab = cum; break; }
            cum += c;
        }
        s_B = B; s_nab = (B>=0) ? nab : cum;
        if (B < 0){ s_cut = __float_as_uint(SCORE_T); s_r = 0; }
    }
    __syncthreads();
    const int B = s_B;

    if (B >= 0){
        const unsigned Bfull = (unsigned)(B + B_LO);
        for (int i=t; i<256; i+=1024) hist[i] = 0;
        __syncthreads();
        for (int i=t; i<n; i+=1024){
            unsigned u = (unsigned)(g_cand[i] >> 32);
            if ((u >> 16) == Bfull) atomicAdd(&hist[(u >> 8) & 255u], 1);
        }
        __syncthreads();
        if (t==0){
            int cum = s_nab, b1 = 0;
            for (int q=255; q>=0; q--){ int c=hist[q]; if (cum + c >= MSEL){ b1=q; break; } cum += c; }
            s_sub = b1; s_nab = cum;
        }
        __syncthreads();
        const unsigned pfx = (Bfull << 8) | (unsigned)s_sub;
        for (int i=t; i<256; i+=1024) hist[i] = 0;
        __syncthreads();
        for (int i=t; i<n; i+=1024){
            unsigned u = (unsigned)(g_cand[i] >> 32);
            if ((u >> 8) == pfx) atomicAdd(&hist[u & 255u], 1);
        }
        __syncthreads();
        if (t==0){
            int cum = s_nab, b0 = 0;
            for (int q=255; q>=0; q--){ int c=hist[q]; if (cum + c >= MSEL){ b0=q; break; } cum += c; }
            s_cut = (pfx << 8) | (unsigned)b0;
            s_r = MSEL - cum;
        }
        __syncthreads();
    }

    const unsigned cut = s_cut;
    for (int i=t; i<n; i+=1024){
        unsigned long long key = g_cand[i];
        unsigned u   = (unsigned)(key >> 32);
        unsigned idx = (unsigned)key;
        if (u > cut){
            int p = atomicAdd(&s_nSel, 1);
            sel[p] = ((unsigned long long)(~(u | 0x80000000u)) << 32) | idx;
        } else if (u == cut){
            int p = atomicAdd(&s_nEq, 1);
            if (p < EQ_CAP) se[p] = idx;
        }
    }
    __syncthreads();

    int r = s_r;
    if (r > 0){
        int ne = min(s_nEq, EQ_CAP);
        int np = 1; while (np < ne) np <<= 1;
        for (int i=t; i<np; i+=1024) if (i >= ne) se[i] = 0xFFFFFFFFu;
        __syncthreads();
        for (int k=2;k<=np;k<<=1)
            for (int j=k>>1;j>0;j>>=1){
                for (int base=0; base<np; base+=1024){
                    int i = base+t;
                    if (i < np){
                        int l = i^j;
                        if (l > i && l < np){
                            unsigned a = se[i], bb = se[l];
                            bool asc = (i & k) == 0;
                            if ((a > bb) == asc){ se[i]=bb; se[l]=a; }
                        }
                    }
                }
                __syncthreads();
            }
        unsigned long long hi = (unsigned long long)(~(cut | 0x80000000u)) << 32;
        int base = s_nSel;
        for (int i=t; i<r; i+=1024) sel[base+i] = hi | se[i];
        __syncthreads();
        if (t==0) s_nSel += r;
        __syncthreads();
    }

    if (s_nSel < MSEL){
        __shared__ int wtot[32];
        __shared__ int scnt;
        if (t==0) scnt = s_nSel;
        __syncthreads();
        int lane = t & 31, wd = t >> 5;
        for (int base=0; base<NFLAT; base+=1024){
            int i = base + t;
            bool f = (i < NFLAT) && !(g_probs[i] > SCORE_T);
            unsigned bal = __ballot_sync(0xffffffffu, f);
            if (lane==0) wtot[wd] = __popc(bal);
            __syncthreads();
            int off = scnt;
            for (int w2=0; w2<wd; w2++) off += wtot[w2];
            int slot = off + __popc(bal & ((1u<<lane)-1u));
            if (f && slot < MSEL)
                sel[slot] = ((unsigned long long)0xBF800000u << 32) | (unsigned)i;
            __syncthreads();
            if (t==0){ int tt=0; for (int w2=0;w2<32;w2++) tt+=wtot[w2]; scnt += tt; }
            __syncthreads();
            if (scnt >= MSEL) break;
        }
    }
    __syncthreads();

    for (int k=2;k<=MSEL;k<<=1)
        for (int j=k>>1;j>0;j>>=1){
            #pragma unroll
            for (int base=0; base<MSEL; base+=1024){
                int i = base+t, l = i^j;
                if (l > i){
                    unsigned long long a = sel[i], bb = sel[l];
                    bool asc = (i & k) == 0;
                    if ((a > bb) == asc){ sel[i]=bb; sel[l]=a; }
                }
            }
            __syncthreads();
        }
    for (int i=t; i<MSEL; i+=1024) g_sel[i] = sel[i];

    // reset state for next replay (deterministic across graph replays)
    for (int i=t; i<B_N; i+=1024) g_hist1[i] = 0;
    if (t==0) d_nCand = 0;
}

// ---------------- K3: per-candidate bbox dot + decode + clip + offset ----------------
__global__ __launch_bounds__(128) void k_decode(
    const float* __restrict__ x, const float* __restrict__ bb, const float* __restrict__ prop)
{
    int rank = blockIdx.x;
    int t = threadIdx.x;
    unsigned long long key = g_sel[rank];
    unsigned idx = (unsigned)key;
    int row = (int)(idx / KCLS);
    int cls = (int)(idx - (unsigned)row*KCLS);
    const float* xr = x + (size_t)row*DDIM;
    const float4* wt = g_bwT + (size_t)cls*DDIM;
    float a0=0.f,a1=0.f,a2=0.f,a3=0.f;
    #pragma unroll
    for (int k=t; k<DDIM; k+=128){
        float xv = xr[k];
        float4 wv = wt[k];
        a0 = fmaf(xv, wv.x, a0);
        a1 = fmaf(xv, wv.y, a1);
        a2 = fmaf(xv, wv.z, a2);
        a3 = fmaf(xv, wv.w, a3);
    }
    #pragma unroll
    for (int o=16;o;o>>=1){
        a0 += __shfl_down_sync(0xffffffffu, a0, o);
        a1 += __shfl_down_sync(0xffffffffu, a1, o);
        a2 += __shfl_down_sync(0xffffffffu, a2, o);
        a3 += __shfl_down_sync(0xffffffffu, a3, o);
    }
    __shared__ float red[4][4];
    if ((t & 31) == 0){ int w=t>>5; red[w][0]=a0; red[w][1]=a1; red[w][2]=a2; red[w][3]=a3; }
    __syncthreads();
    if (t == 0){
        int c4 = cls*4;
        float d0 = bb[c4+0] + red[0][0]+red[1][0]+red[2][0]+red[3][0];
        float d1 = bb[c4+1] + red[0][1]+red[1][1]+red[2][1]+red[3][1];
        float d2 = bb[c4+2] + red[0][2]+red[1][2]+red[2][2]+red[3][2];
        float d3 = bb[c4+3] + red[0][3]+red[1][3]+red[2][3]+red[3][3];
        float px1 = prop[row*4+0], py1 = prop[row*4+1];
        float px2 = prop[row*4+2], py2 = prop[row*4+3];
        float w  = px2 - px1, h = py2 - py1;
        float cx = px1 + 0.5f*w, cy = py1 + 0.5f*h;
        float dx = d0 / 10.0f, dy = d1 / 10.0f;
        float dw = fminf(d2 / 5.0f, SCALE_CLAMP);
        float dh = fminf(d3 / 5.0f, SCALE_CLAMP);
        float pcx = dx*w + cx, pcy = dy*h + cy;
        float pw = expf(dw)*w, ph = expf(dh)*h;
        float x1 = pcx - 0.5f*pw, y1 = pcy - 0.5f*ph;
        float x2 = pcx + 0.5f*pw, y2 = pcy + 0.5f*ph;
        x1 = fminf(fmaxf(x1, 0.f), IMG_W);
        x2 = fminf(fmaxf(x2, 0.f), IMG_W);
        y1 = fminf(fmaxf(y1, 0.f), IMG_H);
        y2 = fminf(fmaxf(y2, 0.f), IMG_H);
        g_boxes[rank*4+0]=x1; g_boxes[rank*4+1]=y1;
        g_boxes[rank*4+2]=x2; g_boxes[rank*4+3]=y2;
        float off = (float)cls * MAX_COORD;
        g_obox[rank*4+0]=x1+off; g_obox[rank*4+1]=y1+off;
        g_obox[rank*4+2]=x2+off; g_obox[rank*4+3]=y2+off;
        g_cls[rank] = cls;
        float p = g_probs[idx];
        bool v = p > SCORE_T;
        g_score[rank] = v ? p : -1.0f;
        g_valid[rank] = v ? 1 : 0;
    }
}

// ---------------- K4: per-class NMS + (last block) top-100 output ----------------
__global__ __launch_bounds__(256) void k_nms_out(float* out){
    const int c = blockIdx.x;
    const int t = threadIdx.x;
    __shared__ float4 sb[MSEL];
    __shared__ short srk[MSEL];
    __shared__ unsigned char ssup[MSEL];
    __shared__ int s_n;
    __shared__ int wcnt[8];
    if (t==0) s_n = 0;
    __syncthreads();
    int lane = t & 31, wd = t >> 5;
    for (int base=0; base<MSEL; base+=256){
        int i = base + t;
        bool f = g_valid[i] && (g_cls[i] == c);
        unsigned bal = __ballot_sync(0xffffffffu, f);
        if (lane==0) wcnt[wd] = __popc(bal);
        __syncthreads();
        int off = s_n;
        for (int w2=0; w2<wd; w2++) off += wcnt[w2];
        if (f){
            int pos = off + __popc(bal & ((1u<<lane)-1u));
            sb[pos]  = *(const float4*)&g_obox[i*4];
            srk[pos] = (short)i;
            ssup[pos]= 0;
        }
        __syncthreads();
        if (t==0){ int tt=0; for (int w2=0;w2<8;w2++) tt+=wcnt[w2]; s_n += tt; }
        __syncthreads();
    }
    const int n = s_n;
    for (int k=0; k<n; k++){
        __syncthreads();
        if (ssup[k]) continue;
        float4 bk = sb[k];
        float ak = (bk.z - bk.x) * (bk.w - bk.y);
        for (int j=k+1+t; j<n; j+=256){
            if (ssup[j]) continue;
            float4 bj = sb[j];
            float xx1 = fmaxf(bk.x, bj.x), yy1 = fmaxf(bk.y, bj.y);
            float xx2 = fminf(bk.z, bj.z), yy2 = fminf(bk.w, bj.w);
            float inter = fmaxf(xx2-xx1, 0.f) * fmaxf(yy2-yy1, 0.f);
            float aj = (bj.z - bj.x) * (bj.w - bj.y);
            float un = fmaxf(ak + aj - inter, 1e-9f);
            if (inter / un > 0.5f) ssup[j] = 1;
        }
    }
    __syncthreads();
    for (int j=t; j<n; j+=256) if (ssup[j]) g_sup[srk[j]] = 1;

    // -------- last-block-done: final top-100 scan + output --------
    __threadfence();
    __shared__ int s_last;
    __syncthreads();
    if (t==0) s_last = (atomicAdd(&d_done, 1) == KCLS-1) ? 1 : 0;
    __syncthreads();
    if (!s_last) return;

    // 256 threads, 8 entries each
    unsigned char keep8[8];
    int cnt = 0;
    #pragma unroll
    for (int j=0;j<8;j++){
        int i = t*8 + j;
        unsigned char k = (g_valid[i] && !g_sup[i]) ? 1 : 0;
        keep8[j] = k; cnt += k;
        g_sup[i] = 0;                      // reset for next replay
    }
    __shared__ int warpS[8];
    __shared__ int s_tot;
    int v = cnt;
    #pragma unroll
    for (int o=1;o<32;o<<=1){ int nn = __shfl_up_sync(0xffffffffu, v, o); if (lane>=o) v += nn; }
    if (lane==31) warpS[wd] = v;
    __syncthreads();
    if (t==0){
        int acc=0;
        #pragma unroll
        for (int w2=0;w2<8;w2++){ int tmp=warpS[w2]; warpS[w2]=acc; acc+=tmp; }
        s_tot = acc;
    }
    __syncthreads();
    int kept = (v - cnt) + warpS[wd];       // exclusive keep-prefix at entry t*8
    const int nK = s_tot;
    #pragma unroll
    for (int j=0;j<8;j++){
        int i = t*8 + j;
        int slot = keep8[j] ? kept : (nK + (i - kept));
        if (slot < TOPK){
            out[slot*4+0] = g_boxes[i*4+0];
            out[slot*4+1] = g_boxes[i*4+1];
            out[slot*4+2] = g_boxes[i*4+2];
            out[slot*4+3] = g_boxes[i*4+3];
            out[400+slot] = keep8[j] ? g_score[i] : -1.0f;
            out[500+slot] = (float)g_cls[i];
            out[600+slot] = keep8[j] ? 1.0f : 0.0f;
        }
        kept += keep8[j];
    }
    if (t==0) d_done = 0;                   // reset for next replay
}

// ---------------- launch ----------------
extern "C" void kernel_launch(void* const* d_in, const int* in_sizes, int n_in,
                              void* d_out, int out_size){
    const float* x    = (const float*)d_in[0];
    const float* clsw = (const float*)d_in[1];
    const float* clsb = (const float*)d_in[2];
    const float* bw   = (const float*)d_in[3];
    const float* bbias= (const float*)d_in[4];
    const float* prop = (const float*)d_in[5];
    float* out = (float*)d_out;

    k_gemm_softmax<<<GEMM_BLOCKS + TRANS_BLOCKS, 256>>>(x, clsw, clsb, bw);
    k_select<<<1, 1024>>>();
    k_decode<<<MSEL, 128>>>(x, bbias, prop);
    k_nms_out<<<KCLS, 256>>>(out);
}